// round 3
// baseline (speedup 1.0000x reference)
#include <cuda_runtime.h>

// Problem constants
#define NB 16            // batch B
#define TT 12            // T_IN
#define TO 24            // T_TOTAL
#define NN 5000          // nodes
#define CC 4             // channels
#define KK 16            // neighbors
#define HH 4             // heads
#define BT (NB * TT)     // 192
#define DIN (TT * HH)    // 48
#define DOUT (TO - TT)   // 12
#define NT 2             // nodes per block in main kernel
#define AGG_STRIDE 17                      // 16 (h*4+c) + 1 pad
#define AGG_NL (BT * AGG_STRIDE + 1)       // extra +1 so node stride != 0 mod 32

// Scratch: x transposed to [N][B*T] of float4 (c contiguous). 15.36 MB, L2-resident.
__device__ float4 g_xt[NN * BT];

// ---------------------------------------------------------------------------
// Kernel 1: transpose x [B,T,N,C] -> xt [N, B*T, C]  AND copy x into out[:, :12]
// 32x32 float4 shared tile; all global reads/writes coalesced.
// ---------------------------------------------------------------------------
__global__ void __launch_bounds__(1024) transpose_copy_kernel(
    const float* __restrict__ x, float* __restrict__ out)
{
    __shared__ float4 tile[32][33];
    const float4* __restrict__ x4 = (const float4*)x;
    float4* __restrict__ out4 = (float4*)out;

    int tx = threadIdx.x, ty = threadIdx.y;
    int n  = blockIdx.x * 32 + tx;
    int bt = blockIdx.y * 32 + ty;          // gridDim.y*32 == 192 exactly

    if (n < NN) {
        float4 v = x4[bt * NN + n];
        tile[ty][tx] = v;
        int b = bt / TT, t = bt - b * TT;
        out4[(b * TO + t) * NN + n] = v;    // out[:, :12] = x (coalesced)
    }
    __syncthreads();

    int n2  = blockIdx.x * 32 + ty;
    int bt2 = blockIdx.y * 32 + tx;
    if (n2 < NN) {
        g_xt[n2 * BT + bt2] = tile[tx][ty]; // coalesced write along bt
    }
}

// ---------------------------------------------------------------------------
// Kernel 2: per node-pair — exp weights, coalesced K-gather + aggregation,
// 48x12 matmul epilogue with ReLU, write out[:, 12:].
// ---------------------------------------------------------------------------
__global__ void __launch_bounds__(BT) gnn_main_kernel(
    const float* __restrict__ dists, const int* __restrict__ neighbors,
    const float* __restrict__ W, const float* __restrict__ bias,
    float* __restrict__ out)
{
    __shared__ float agg_s[NT * AGG_NL];     // [nl][bt][h*4+c], padded
    __shared__ float w_s[NT][KK][HH];
    __shared__ int   nbr_s[NT][KK];
    __shared__ float W_s[DIN * DOUT];
    __shared__ float b_s[DOUT];

    const int tid = threadIdx.x;             // 0..191
    const int n0  = blockIdx.x * NT;

    // --- Phase 0: weights, neighbor indices, W, b into shared ---
    if (tid < NT * KK) {
        int nl = tid / KK, k = tid - nl * KK;
        float d = dists[(n0 + nl) * KK + k];
        nbr_s[nl][k] = neighbors[(n0 + nl) * KK + k];
        float p = d * d * (1.0f / 36.0f);    // d^2 / sigma^2
        w_s[nl][k][0] = __expf(-0.25f * p);
        w_s[nl][k][1] = __expf(-0.50f * p);
        w_s[nl][k][2] = __expf(-0.75f * p);
        w_s[nl][k][3] = __expf(-p);
    }
    for (int i = tid; i < DIN * DOUT; i += BT) W_s[i] = W[i];
    if (tid < DOUT) b_s[tid] = bias[tid];
    __syncthreads();

    // --- Phase 1: gather + weighted aggregation ---
    // Thread = one (b,t). 16 coalesced float4 loads from xt per node.
    #pragma unroll
    for (int nl = 0; nl < NT; ++nl) {
        const int bt = tid;
        float4 a0 = make_float4(0.f, 0.f, 0.f, 0.f);
        float4 a1 = a0, a2 = a0, a3 = a0;
        #pragma unroll
        for (int k = 0; k < KK; ++k) {
            int nb = nbr_s[nl][k];
            float4 xv = g_xt[nb * BT + bt];
            float w0 = w_s[nl][k][0];
            float w1 = w_s[nl][k][1];
            float w2 = w_s[nl][k][2];
            float w3 = w_s[nl][k][3];
            a0.x = fmaf(xv.x, w0, a0.x); a0.y = fmaf(xv.y, w0, a0.y);
            a0.z = fmaf(xv.z, w0, a0.z); a0.w = fmaf(xv.w, w0, a0.w);
            a1.x = fmaf(xv.x, w1, a1.x); a1.y = fmaf(xv.y, w1, a1.y);
            a1.z = fmaf(xv.z, w1, a1.z); a1.w = fmaf(xv.w, w1, a1.w);
            a2.x = fmaf(xv.x, w2, a2.x); a2.y = fmaf(xv.y, w2, a2.y);
            a2.z = fmaf(xv.z, w2, a2.z); a2.w = fmaf(xv.w, w2, a2.w);
            a3.x = fmaf(xv.x, w3, a3.x); a3.y = fmaf(xv.y, w3, a3.y);
            a3.z = fmaf(xv.z, w3, a3.z); a3.w = fmaf(xv.w, w3, a3.w);
        }
        float* ap = agg_s + nl * AGG_NL + bt * AGG_STRIDE;
        ap[0]  = a0.x; ap[1]  = a0.y; ap[2]  = a0.z; ap[3]  = a0.w;
        ap[4]  = a1.x; ap[5]  = a1.y; ap[6]  = a1.z; ap[7]  = a1.w;
        ap[8]  = a2.x; ap[9]  = a2.y; ap[10] = a2.z; ap[11] = a2.w;
        ap[12] = a3.x; ap[13] = a3.y; ap[14] = a3.z; ap[15] = a3.w;
    }
    __syncthreads();

    // --- Phase 2: y[b, n, c, o] = relu(sum_{t,h} agg[b,t,h,c] * W[t*H+h, o] + b[o])
    // unit u = (b*12 + o)*2 + nl ; each thread does 2 units; one float4 store each.
    float4* __restrict__ out4 = (float4*)out;
    #pragma unroll
    for (int j = 0; j < NT * NB * DOUT / BT; ++j) {
        int u  = tid + j * BT;               // 0..383
        int nl = u & 1;
        int bo = u >> 1;                     // b*12 + o
        int o  = bo % DOUT;
        int b  = bo / DOUT;

        float acc0 = b_s[o], acc1 = b_s[o], acc2 = b_s[o], acc3 = b_s[o];
        const float* ag = agg_s + nl * AGG_NL + (b * TT) * AGG_STRIDE;
        #pragma unroll
        for (int t = 0; t < TT; ++t) {
            const float* a = ag + t * AGG_STRIDE;
            #pragma unroll
            for (int h = 0; h < HH; ++h) {
                float wv = W_s[(t * HH + h) * DOUT + o];
                acc0 = fmaf(a[h * 4 + 0], wv, acc0);
                acc1 = fmaf(a[h * 4 + 1], wv, acc1);
                acc2 = fmaf(a[h * 4 + 2], wv, acc2);
                acc3 = fmaf(a[h * 4 + 3], wv, acc3);
            }
        }
        float4 y;
        y.x = fmaxf(acc0, 0.f);
        y.y = fmaxf(acc1, 0.f);
        y.z = fmaxf(acc2, 0.f);
        y.w = fmaxf(acc3, 0.f);
        out4[(b * TO + TT + o) * NN + (n0 + nl)] = y;
    }
}

// ---------------------------------------------------------------------------
// metadata order: x (f32, 3840000), dists (f32, 80000), W (f32, 576),
//                 b (f32, 12), neighbors (i32, 80000); output f32 (7680000)
// ---------------------------------------------------------------------------
extern "C" void kernel_launch(void* const* d_in, const int* in_sizes, int n_in,
                              void* d_out, int out_size)
{
    const float* x         = (const float*)d_in[0];
    const float* dists     = (const float*)d_in[1];
    const float* W         = (const float*)d_in[2];
    const float* bias      = (const float*)d_in[3];
    const int*   neighbors = (const int*)d_in[4];
    float* out = (float*)d_out;

    dim3 tb(32, 32);
    dim3 tg((NN + 31) / 32, BT / 32);        // 157 x 6
    transpose_copy_kernel<<<tg, tb>>>(x, out);

    gnn_main_kernel<<<NN / NT, BT>>>(dists, neighbors, W, bias, out);
}

// round 4
// speedup vs baseline: 1.4495x; 1.4495x over previous
#include <cuda_runtime.h>
#include <cuda_fp16.h>

// Problem constants
#define NB 16            // batch B
#define TT 12            // T_IN
#define TO 24            // T_TOTAL
#define NN 5000          // nodes
#define CC 4             // channels
#define KK 16            // neighbors
#define HH 4             // heads
#define BT (NB * TT)     // 192
#define BTP (BT / 2)     // 96 bt-pairs
#define DIN (TT * HH)    // 48
#define DOUT (TO - TT)   // 12
#define NT 2             // nodes per block
#define THREADS 96

// agg shared layout: per b-group of 12 rows, row stride 20 floats (80B, 16B aligned),
// +4 pad per group so consecutive b start at distinct banks (244 mod 32 = 20).
#define AGG_B 244                    // floats per b-group
#define AGG_NL (NB * AGG_B + 16)     // 3920 floats per node region (16B-aligned, bank skew)

// Scratch: x transposed+converted to fp16: [N][btp][8 halfs] = [N][96] uint4. 7.68 MB, L2-resident.
__device__ uint4 g_xt[NN * BTP];

static __device__ __forceinline__ float2 h2f(unsigned u) {
    __half2 h = *reinterpret_cast<__half2*>(&u);
    return __half22float2(h);
}

// ---------------------------------------------------------------------------
// Kernel 1: x [B,T,N,C] f32 -> xt [N][btp] fp16 (transposed)  AND out[:, :12] = x
// ---------------------------------------------------------------------------
__global__ void __launch_bounds__(1024) transpose_convert_kernel(
    const float* __restrict__ x, float* __restrict__ out)
{
    __shared__ uint2 tile[32][33];
    const float4* __restrict__ x4 = (const float4*)x;
    float4* __restrict__ out4 = (float4*)out;

    int tx = threadIdx.x, ty = threadIdx.y;
    int n  = blockIdx.x * 32 + tx;
    int bt = blockIdx.y * 32 + ty;          // gridDim.y*32 == 192 exactly

    if (n < NN) {
        float4 v = x4[bt * NN + n];
        __half2 h01 = __floats2half2_rn(v.x, v.y);
        __half2 h23 = __floats2half2_rn(v.z, v.w);
        uint2 u;
        u.x = *reinterpret_cast<unsigned*>(&h01);
        u.y = *reinterpret_cast<unsigned*>(&h23);
        tile[ty][tx] = u;
        int b = bt / TT, t = bt - b * TT;
        out4[(b * TO + t) * NN + n] = v;    // out[:, :12] = x (coalesced)
    }
    __syncthreads();

    if (tx < 16) {
        int n2 = blockIdx.x * 32 + ty;
        if (n2 < NN) {
            int btp = blockIdx.y * 16 + tx;
            uint2 a = tile[2 * tx][ty];
            uint2 b2 = tile[2 * tx + 1][ty];
            g_xt[n2 * BTP + btp] = make_uint4(a.x, a.y, b2.x, b2.y);
        }
    }
}

// ---------------------------------------------------------------------------
// Kernel 2: per node-pair — exp weights, coalesced fp16 K-gather + aggregation
// (fp32 accum), vectorized 48x12 matmul epilogue with ReLU.
// ---------------------------------------------------------------------------
__global__ void __launch_bounds__(THREADS) gnn_main_kernel(
    const float* __restrict__ dists, const int* __restrict__ neighbors,
    const float* __restrict__ W, const float* __restrict__ bias,
    float* __restrict__ out)
{
    __shared__ __align__(16) float agg_s[NT * AGG_NL];
    __shared__ __align__(16) float W_s[DIN * DOUT];
    __shared__ float w_s[NT][KK][HH];
    __shared__ int   nbr_s[NT][KK];
    __shared__ float b_s[DOUT];

    const int tid = threadIdx.x;             // 0..95
    const int n0  = blockIdx.x * NT;

    // --- Phase 0: exp weights, neighbor indices, W, bias into shared ---
    if (tid < NT * KK) {
        int nl = tid >> 4, k = tid & 15;
        float d = dists[(n0 + nl) * KK + k];
        nbr_s[nl][k] = neighbors[(n0 + nl) * KK + k];
        float p = d * d * (1.0f / 36.0f);    // d^2 / sigma^2
        w_s[nl][k][0] = __expf(-0.25f * p);
        w_s[nl][k][1] = __expf(-0.50f * p);
        w_s[nl][k][2] = __expf(-0.75f * p);
        w_s[nl][k][3] = __expf(-p);
    }
    #pragma unroll
    for (int i = tid; i < DIN * DOUT; i += THREADS) W_s[i] = W[i];
    if (tid < DOUT) b_s[tid] = bias[tid];
    __syncthreads();

    // --- Phase 1: fp16 gather + weighted aggregation (fp32 accum) ---
    // Thread owns bt-pair (2*tid, 2*tid+1); loops both nodes.
    {
        const int btp = tid;
        const int bt0 = btp * 2;
        const int b0 = bt0 / TT, t0 = bt0 - b0 * TT;
        const int bt1 = bt0 + 1;
        const int b1 = bt1 / TT, t1 = bt1 - b1 * TT;

        #pragma unroll
        for (int nl = 0; nl < NT; ++nl) {
            float acc[2][HH][CC];
            #pragma unroll
            for (int p = 0; p < 2; ++p)
                #pragma unroll
                for (int h = 0; h < HH; ++h)
                    #pragma unroll
                    for (int c = 0; c < CC; ++c) acc[p][h][c] = 0.f;

            #pragma unroll
            for (int k = 0; k < KK; ++k) {
                uint4 raw = g_xt[nbr_s[nl][k] * BTP + btp];
                float2 p00 = h2f(raw.x);   // bt0: c0,c1
                float2 p01 = h2f(raw.y);   // bt0: c2,c3
                float2 p10 = h2f(raw.z);   // bt1: c0,c1
                float2 p11 = h2f(raw.w);   // bt1: c2,c3
                #pragma unroll
                for (int h = 0; h < HH; ++h) {
                    float w = w_s[nl][k][h];
                    acc[0][h][0] = fmaf(p00.x, w, acc[0][h][0]);
                    acc[0][h][1] = fmaf(p00.y, w, acc[0][h][1]);
                    acc[0][h][2] = fmaf(p01.x, w, acc[0][h][2]);
                    acc[0][h][3] = fmaf(p01.y, w, acc[0][h][3]);
                    acc[1][h][0] = fmaf(p10.x, w, acc[1][h][0]);
                    acc[1][h][1] = fmaf(p10.y, w, acc[1][h][1]);
                    acc[1][h][2] = fmaf(p11.x, w, acc[1][h][2]);
                    acc[1][h][3] = fmaf(p11.y, w, acc[1][h][3]);
                }
            }
            float* r0 = agg_s + nl * AGG_NL + b0 * AGG_B + t0 * 20;
            float* r1 = agg_s + nl * AGG_NL + b1 * AGG_B + t1 * 20;
            #pragma unroll
            for (int h = 0; h < HH; ++h) {
                *(float4*)(r0 + h * 4) =
                    make_float4(acc[0][h][0], acc[0][h][1], acc[0][h][2], acc[0][h][3]);
                *(float4*)(r1 + h * 4) =
                    make_float4(acc[1][h][0], acc[1][h][1], acc[1][h][2], acc[1][h][3]);
            }
        }
    }
    __syncthreads();

    // --- Phase 2: y[b,n,c,o] = relu(sum_{t,h} agg[b,t,h,c] * W[t*H+h,o] + b[o])
    // Thread owns (nl, b, o-quad): 2*16*3 = 96 units. Inner loop: 2x LDS.128 + 16 FMA.
    {
        const int nl = tid & 1;
        const int bq = tid >> 1;             // 0..47
        const int b  = bq / 3;
        const int oq = bq - b * 3;           // o-quad: o = 4*oq..4*oq+3

        float acc[4][CC];                    // [o_local][c]
        #pragma unroll
        for (int i = 0; i < 4; ++i) {
            float bv = b_s[oq * 4 + i];
            acc[i][0] = bv; acc[i][1] = bv; acc[i][2] = bv; acc[i][3] = bv;
        }

        const float* abase = agg_s + nl * AGG_NL + b * AGG_B;
        const float* wbase = W_s + oq * 4;
        #pragma unroll
        for (int t = 0; t < TT; ++t) {
            #pragma unroll
            for (int h = 0; h < HH; ++h) {
                float4 a  = *(const float4*)(abase + t * 20 + h * 4);
                float4 wv = *(const float4*)(wbase + (t * HH + h) * DOUT);
                acc[0][0] = fmaf(a.x, wv.x, acc[0][0]);
                acc[0][1] = fmaf(a.y, wv.x, acc[0][1]);
                acc[0][2] = fmaf(a.z, wv.x, acc[0][2]);
                acc[0][3] = fmaf(a.w, wv.x, acc[0][3]);
                acc[1][0] = fmaf(a.x, wv.y, acc[1][0]);
                acc[1][1] = fmaf(a.y, wv.y, acc[1][1]);
                acc[1][2] = fmaf(a.z, wv.y, acc[1][2]);
                acc[1][3] = fmaf(a.w, wv.y, acc[1][3]);
                acc[2][0] = fmaf(a.x, wv.z, acc[2][0]);
                acc[2][1] = fmaf(a.y, wv.z, acc[2][1]);
                acc[2][2] = fmaf(a.z, wv.z, acc[2][2]);
                acc[2][3] = fmaf(a.w, wv.z, acc[2][3]);
                acc[3][0] = fmaf(a.x, wv.w, acc[3][0]);
                acc[3][1] = fmaf(a.y, wv.w, acc[3][1]);
                acc[3][2] = fmaf(a.z, wv.w, acc[3][2]);
                acc[3][3] = fmaf(a.w, wv.w, acc[3][3]);
            }
        }

        float4* __restrict__ out4 = (float4*)out;
        #pragma unroll
        for (int i = 0; i < 4; ++i) {
            int o = oq * 4 + i;
            float4 y;
            y.x = fmaxf(acc[i][0], 0.f);
            y.y = fmaxf(acc[i][1], 0.f);
            y.z = fmaxf(acc[i][2], 0.f);
            y.w = fmaxf(acc[i][3], 0.f);
            out4[(b * TO + TT + o) * NN + (n0 + nl)] = y;
        }
    }
}

// ---------------------------------------------------------------------------
// metadata order: x (f32), dists (f32), W (f32), b (f32), neighbors (i32);
// output f32 (7680000)
// ---------------------------------------------------------------------------
extern "C" void kernel_launch(void* const* d_in, const int* in_sizes, int n_in,
                              void* d_out, int out_size)
{
    const float* x         = (const float*)d_in[0];
    const float* dists     = (const float*)d_in[1];
    const float* W         = (const float*)d_in[2];
    const float* bias      = (const float*)d_in[3];
    const int*   neighbors = (const int*)d_in[4];
    float* out = (float*)d_out;

    dim3 tb(32, 32);
    dim3 tg((NN + 31) / 32, BT / 32);        // 157 x 6
    transpose_convert_kernel<<<tg, tb>>>(x, out);

    gnn_main_kernel<<<NN / NT, THREADS>>>(dists, neighbors, W, bias, out);
}

// round 5
// speedup vs baseline: 1.4547x; 1.0036x over previous
#include <cuda_runtime.h>
#include <cuda_fp16.h>

// Problem constants
#define NB 16            // batch B
#define TT 12            // T_IN
#define TO 24            // T_TOTAL
#define NN 5000          // nodes
#define CC 4             // channels
#define KK 16            // neighbors
#define HH 4             // heads
#define BT (NB * TT)     // 192
#define BTP (BT / 2)     // 96 bt-pairs
#define DIN (TT * HH)    // 48
#define DOUT (TO - TT)   // 12
#define NT 2             // nodes per block
#define THREADS 192

// agg shared layout: per b-group, row stride 20 floats (80B, 16B aligned),
// b stride 244 (mod 32 = 20), node stride 3920 (mod 32 = 16) -> the six
// (nl,b) combos touched by one warp in phase 2 hit disjoint bank quads.
#define AGG_B 244                    // floats per b-group
#define AGG_NL (NB * AGG_B + 16)     // 3920 floats per node region

// Scratch: x transposed+converted to fp16: [N][btp][8 halfs]. 7.68 MB, L2-resident.
__device__ uint4 g_xt[NN * BTP];

static __device__ __forceinline__ float2 h2f(unsigned u) {
    __half2 h = *reinterpret_cast<__half2*>(&u);
    return __half22float2(h);
}

// ---------------------------------------------------------------------------
// Kernel 1: x [B,T,N,C] f32 -> xt [N][btp] fp16 (transposed)  AND out[:, :12] = x
// ---------------------------------------------------------------------------
__global__ void __launch_bounds__(1024) transpose_convert_kernel(
    const float* __restrict__ x, float* __restrict__ out)
{
    __shared__ uint2 tile[32][33];
    const float4* __restrict__ x4 = (const float4*)x;
    float4* __restrict__ out4 = (float4*)out;

    int tx = threadIdx.x, ty = threadIdx.y;
    int n  = blockIdx.x * 32 + tx;
    int bt = blockIdx.y * 32 + ty;          // gridDim.y*32 == 192 exactly

    if (n < NN) {
        float4 v = x4[bt * NN + n];
        __half2 h01 = __floats2half2_rn(v.x, v.y);
        __half2 h23 = __floats2half2_rn(v.z, v.w);
        uint2 u;
        u.x = *reinterpret_cast<unsigned*>(&h01);
        u.y = *reinterpret_cast<unsigned*>(&h23);
        tile[ty][tx] = u;
        int b = bt / TT, t = bt - b * TT;
        out4[(b * TO + t) * NN + n] = v;    // out[:, :12] = x (coalesced)
    }
    __syncthreads();

    if (tx < 16) {
        int n2 = blockIdx.x * 32 + ty;
        if (n2 < NN) {
            int btp = blockIdx.y * 16 + tx;
            uint2 a  = tile[2 * tx][ty];
            uint2 b2 = tile[2 * tx + 1][ty];
            g_xt[n2 * BTP + btp] = make_uint4(a.x, a.y, b2.x, b2.y);
        }
    }
}

// ---------------------------------------------------------------------------
// Kernel 2: per node-pair. 192 threads:
//   phase 1: thread = (nl, btp)   -> fp16 gather + weighted agg (fp32 accum)
//   phase 2: thread = (nl, b, op) -> 48x12 matmul (o-pair), ReLU, store
// ---------------------------------------------------------------------------
__global__ void __launch_bounds__(THREADS, 5) gnn_main_kernel(
    const float* __restrict__ dists, const int* __restrict__ neighbors,
    const float* __restrict__ W, const float* __restrict__ bias,
    float* __restrict__ out)
{
    __shared__ __align__(16) float agg_s[NT * AGG_NL];
    __shared__ __align__(16) float W_s[DIN * DOUT];
    __shared__ __align__(16) float w_s[NT][KK][HH];
    __shared__ int   nbr_s[NT][KK];
    __shared__ float b_s[DOUT];

    const int tid = threadIdx.x;             // 0..191
    const int n0  = blockIdx.x * NT;

    // --- Phase 0: exp weights, neighbor indices, W, bias into shared ---
    if (tid < NT * KK) {
        int nl = tid >> 4, k = tid & 15;
        float d = dists[(n0 + nl) * KK + k];
        nbr_s[nl][k] = neighbors[(n0 + nl) * KK + k];
        float p = d * d * (1.0f / 36.0f);    // d^2 / sigma^2
        w_s[nl][k][0] = __expf(-0.25f * p);
        w_s[nl][k][1] = __expf(-0.50f * p);
        w_s[nl][k][2] = __expf(-0.75f * p);
        w_s[nl][k][3] = __expf(-p);
    }
    #pragma unroll
    for (int i = tid; i < DIN * DOUT; i += THREADS) W_s[i] = W[i];
    if (tid < DOUT) b_s[tid] = bias[tid];
    __syncthreads();

    // --- Phase 1: fp16 gather + weighted aggregation (fp32 accum) ---
    // Warp-uniform node: nl = tid/96; lanes cover consecutive btp -> 512B segments.
    {
        const int nl  = tid / BTP;
        const int btp = tid - nl * BTP;
        const int bt0 = btp * 2;
        const int b0 = bt0 / TT, t0 = bt0 - b0 * TT;   // t0 even; t1 = t0+1 same b

        float acc[2][HH][CC];
        #pragma unroll
        for (int p = 0; p < 2; ++p)
            #pragma unroll
            for (int h = 0; h < HH; ++h)
                #pragma unroll
                for (int c = 0; c < CC; ++c) acc[p][h][c] = 0.f;

        #pragma unroll
        for (int k = 0; k < KK; ++k) {
            uint4 raw = g_xt[nbr_s[nl][k] * BTP + btp];
            float2 p00 = h2f(raw.x);   // bt0: c0,c1
            float2 p01 = h2f(raw.y);   // bt0: c2,c3
            float2 p10 = h2f(raw.z);   // bt1: c0,c1
            float2 p11 = h2f(raw.w);   // bt1: c2,c3
            float4 w = *(const float4*)w_s[nl][k];
            acc[0][0][0] = fmaf(p00.x, w.x, acc[0][0][0]);
            acc[0][0][1] = fmaf(p00.y, w.x, acc[0][0][1]);
            acc[0][0][2] = fmaf(p01.x, w.x, acc[0][0][2]);
            acc[0][0][3] = fmaf(p01.y, w.x, acc[0][0][3]);
            acc[0][1][0] = fmaf(p00.x, w.y, acc[0][1][0]);
            acc[0][1][1] = fmaf(p00.y, w.y, acc[0][1][1]);
            acc[0][1][2] = fmaf(p01.x, w.y, acc[0][1][2]);
            acc[0][1][3] = fmaf(p01.y, w.y, acc[0][1][3]);
            acc[0][2][0] = fmaf(p00.x, w.z, acc[0][2][0]);
            acc[0][2][1] = fmaf(p00.y, w.z, acc[0][2][1]);
            acc[0][2][2] = fmaf(p01.x, w.z, acc[0][2][2]);
            acc[0][2][3] = fmaf(p01.y, w.z, acc[0][2][3]);
            acc[0][3][0] = fmaf(p00.x, w.w, acc[0][3][0]);
            acc[0][3][1] = fmaf(p00.y, w.w, acc[0][3][1]);
            acc[0][3][2] = fmaf(p01.x, w.w, acc[0][3][2]);
            acc[0][3][3] = fmaf(p01.y, w.w, acc[0][3][3]);
            acc[1][0][0] = fmaf(p10.x, w.x, acc[1][0][0]);
            acc[1][0][1] = fmaf(p10.y, w.x, acc[1][0][1]);
            acc[1][0][2] = fmaf(p11.x, w.x, acc[1][0][2]);
            acc[1][0][3] = fmaf(p11.y, w.x, acc[1][0][3]);
            acc[1][1][0] = fmaf(p10.x, w.y, acc[1][1][0]);
            acc[1][1][1] = fmaf(p10.y, w.y, acc[1][1][1]);
            acc[1][1][2] = fmaf(p11.x, w.y, acc[1][1][2]);
            acc[1][1][3] = fmaf(p11.y, w.y, acc[1][1][3]);
            acc[1][2][0] = fmaf(p10.x, w.z, acc[1][2][0]);
            acc[1][2][1] = fmaf(p10.y, w.z, acc[1][2][1]);
            acc[1][2][2] = fmaf(p11.x, w.z, acc[1][2][2]);
            acc[1][2][3] = fmaf(p11.y, w.z, acc[1][2][3]);
            acc[1][3][0] = fmaf(p10.x, w.w, acc[1][3][0]);
            acc[1][3][1] = fmaf(p10.y, w.w, acc[1][3][1]);
            acc[1][3][2] = fmaf(p11.x, w.w, acc[1][3][2]);
            acc[1][3][3] = fmaf(p11.y, w.w, acc[1][3][3]);
        }
        float* r0 = agg_s + nl * AGG_NL + b0 * AGG_B + t0 * 20;
        #pragma unroll
        for (int h = 0; h < HH; ++h) {
            *(float4*)(r0 + h * 4) =
                make_float4(acc[0][h][0], acc[0][h][1], acc[0][h][2], acc[0][h][3]);
            *(float4*)(r0 + 20 + h * 4) =
                make_float4(acc[1][h][0], acc[1][h][1], acc[1][h][2], acc[1][h][3]);
        }
    }
    __syncthreads();

    // --- Phase 2: y[b,n,c,o] = relu(sum_{t,h} agg[b,t,h,c] * W[t*H+h,o] + b[o])
    // Thread = (nl, op, b): 2*6*16 = 192 units. Inner: LDS.128 + LDS.64 + 8 FMA.
    {
        const int nl = tid & 1;
        const int r  = tid >> 1;             // 0..95
        const int op = r % 6;                // o-pair: o = 2*op, 2*op+1
        const int b  = r / 6;                // 0..15

        float acc0x = b_s[op * 2],     acc0y = acc0x, acc0z = acc0x, acc0w = acc0x;
        float acc1x = b_s[op * 2 + 1], acc1y = acc1x, acc1z = acc1x, acc1w = acc1x;

        const float* abase = agg_s + nl * AGG_NL + b * AGG_B;
        const float* wbase = W_s + op * 2;
        #pragma unroll
        for (int t = 0; t < TT; ++t) {
            #pragma unroll
            for (int h = 0; h < HH; ++h) {
                float4 a  = *(const float4*)(abase + t * 20 + h * 4);
                float2 wv = *(const float2*)(wbase + (t * HH + h) * DOUT);
                acc0x = fmaf(a.x, wv.x, acc0x);
                acc0y = fmaf(a.y, wv.x, acc0y);
                acc0z = fmaf(a.z, wv.x, acc0z);
                acc0w = fmaf(a.w, wv.x, acc0w);
                acc1x = fmaf(a.x, wv.y, acc1x);
                acc1y = fmaf(a.y, wv.y, acc1y);
                acc1z = fmaf(a.z, wv.y, acc1z);
                acc1w = fmaf(a.w, wv.y, acc1w);
            }
        }

        float4* __restrict__ out4 = (float4*)out;
        float4 y0, y1;
        y0.x = fmaxf(acc0x, 0.f); y0.y = fmaxf(acc0y, 0.f);
        y0.z = fmaxf(acc0z, 0.f); y0.w = fmaxf(acc0w, 0.f);
        y1.x = fmaxf(acc1x, 0.f); y1.y = fmaxf(acc1y, 0.f);
        y1.z = fmaxf(acc1z, 0.f); y1.w = fmaxf(acc1w, 0.f);
        int o0 = op * 2;
        out4[(b * TO + TT + o0) * NN + (n0 + nl)] = y0;
        out4[(b * TO + TT + o0 + 1) * NN + (n0 + nl)] = y1;
    }
}

// ---------------------------------------------------------------------------
// metadata order: x (f32), dists (f32), W (f32), b (f32), neighbors (i32);
// output f32 (7680000)
// ---------------------------------------------------------------------------
extern "C" void kernel_launch(void* const* d_in, const int* in_sizes, int n_in,
                              void* d_out, int out_size)
{
    const float* x         = (const float*)d_in[0];
    const float* dists     = (const float*)d_in[1];
    const float* W         = (const float*)d_in[2];
    const float* bias      = (const float*)d_in[3];
    const int*   neighbors = (const int*)d_in[4];
    float* out = (float*)d_out;

    dim3 tb(32, 32);
    dim3 tg((NN + 31) / 32, BT / 32);        // 157 x 6
    transpose_convert_kernel<<<tg, tb>>>(x, out);

    gnn_main_kernel<<<NN / NT, THREADS>>>(dists, neighbors, W, bias, out);
}